// round 1
// baseline (speedup 1.0000x reference)
#include <cuda_runtime.h>
#include <cuda_bf16.h>
#include <math.h>

#define NROWS 1048576
#define DTOT  64
#define DD    32
#define KK    40
#define BB    5.0f

// Precomputed spline tables (per transformed dim)
__device__ float g_cumw[DD * (KK + 1)];
__device__ float g_cumh[DD * (KK + 1)];
__device__ float g_dv  [DD * (KK + 1)];
__device__ float g_rbw [DD * KK];

// ---------------------------------------------------------------------------
// Precompute: softmax->cumsum for widths/heights, softplus for derivatives.
// One thread per transformed dim; trivial cost.
// ---------------------------------------------------------------------------
__global__ void precompute_tables(const float* __restrict__ w,
                                  const float* __restrict__ h,
                                  const float* __restrict__ dk)
{
    int j = threadIdx.x;
    if (j >= DD) return;

    // widths
    {
        const float* row = w + j * KK;
        float mx = -1e30f;
        for (int k = 0; k < KK; k++) mx = fmaxf(mx, row[k]);
        float s = 0.f;
        for (int k = 0; k < KK; k++) s += expf(row[k] - mx);
        float inv_s = 1.0f / s;
        float cum = -BB;
        g_cumw[j * (KK + 1) + 0] = -BB;
        for (int k = 0; k < KK; k++) {
            float wd = expf(row[k] - mx) * inv_s * (2.0f * BB);
            g_rbw[j * KK + k] = 1.0f / wd;
            cum += wd;
            g_cumw[j * (KK + 1) + k + 1] = cum;
        }
    }
    // heights
    {
        const float* row = h + j * KK;
        float mx = -1e30f;
        for (int k = 0; k < KK; k++) mx = fmaxf(mx, row[k]);
        float s = 0.f;
        for (int k = 0; k < KK; k++) s += expf(row[k] - mx);
        float inv_s = 1.0f / s;
        float cum = -BB;
        g_cumh[j * (KK + 1) + 0] = -BB;
        for (int k = 0; k < KK; k++) {
            float ht = expf(row[k] - mx) * inv_s * (2.0f * BB);
            cum += ht;
            g_cumh[j * (KK + 1) + k + 1] = cum;
        }
    }
    // derivatives: [1, softplus(d_0..d_{K-2}), 1]
    {
        g_dv[j * (KK + 1) + 0]  = 1.0f;
        g_dv[j * (KK + 1) + KK] = 1.0f;
        const float* row = dk + j * (KK - 1);
        for (int k = 0; k < KK - 1; k++) {
            float v = row[k];
            float sp = (v > 20.0f) ? v : log1pf(expf(v));
            g_dv[j * (KK + 1) + k + 1] = sp;
        }
    }
}

// ---------------------------------------------------------------------------
// Main kernel: one warp per row; lane handles cols {lane, lane+32}.
// Tables staged in shared memory once per block; grid-stride over rows.
// ---------------------------------------------------------------------------
__global__ __launch_bounds__(256)
void rqs_forward_kernel(const float* __restrict__ u,
                        const int*   __restrict__ nodes,
                        float* __restrict__ xout,
                        float* __restrict__ logd)
{
    __shared__ float s_cumw[DD * (KK + 1)];
    __shared__ float s_cumh[DD * (KK + 1)];
    __shared__ float s_dv  [DD * (KK + 1)];
    __shared__ float s_rbw [DD * KK];
    __shared__ int   s_inv [DTOT];

    const int tid = threadIdx.x;

    for (int i = tid; i < DD * (KK + 1); i += blockDim.x) {
        s_cumw[i] = g_cumw[i];
        s_cumh[i] = g_cumh[i];
        s_dv[i]   = g_dv[i];
    }
    for (int i = tid; i < DD * KK; i += blockDim.x) s_rbw[i] = g_rbw[i];
    if (tid < DTOT) s_inv[tid] = -1;
    __syncthreads();
    if (tid < DD) s_inv[nodes[tid]] = tid;
    __syncthreads();

    const int lane = tid & 31;
    const int warp = tid >> 5;
    const int rows_per_iter = blockDim.x >> 5;   // 8

    for (unsigned row = blockIdx.x * rows_per_iter + warp; row < NROWS;
         row += gridDim.x * rows_per_iter)
    {
        const float* up = u    + (size_t)row * DTOT;
        float*       xp = xout + (size_t)row * DTOT;
        float acc = 0.0f;

        #pragma unroll
        for (int half = 0; half < 2; half++) {
            const int col = lane + half * 32;
            const float x = __ldg(up + col);
            const int j = s_inv[col];
            float y = x;

            if (j >= 0 && fabsf(x) <= BB) {
                const float xc = x;
                const float* cw = s_cumw + j * (KK + 1);
                // binary search: largest i with cw[i] <= xc (cw[0] = -B <= xc)
                int lo = 0, hi = KK;
                #pragma unroll
                for (int it = 0; it < 6; it++) {
                    int mid = (lo + hi) >> 1;
                    if (cw[mid] <= xc) lo = mid; else hi = mid;
                }
                int idx = min(lo, KK - 1);

                const float cwv = cw[idx];
                const float rbw = s_rbw[j * KK + idx];
                const float ch  = s_cumh[j * (KK + 1) + idx];
                const float bh  = s_cumh[j * (KK + 1) + idx + 1] - ch;
                const float d0  = s_dv[j * (KK + 1) + idx];
                const float d1  = s_dv[j * (KK + 1) + idx + 1];

                const float delta = bh * rbw;
                const float theta = (xc - cwv) * rbw;
                const float omt   = 1.0f - theta;
                const float t1m   = theta * omt;

                const float denom = fmaf(d0 + d1 - 2.0f * delta, t1m, delta);
                const float r     = __fdividef(1.0f, denom);

                y = fmaf(bh * fmaf(delta * theta, theta, d0 * t1m), r, ch);

                const float A = delta * delta *
                    (fmaf(d1 * theta, theta, 2.0f * delta * t1m) + d0 * omt * omt);
                acc += __logf(A * r * r);
            }
            xp[col] = y;
        }

        // warp-level logdet reduction (full row lives in this warp)
        #pragma unroll
        for (int o = 16; o > 0; o >>= 1)
            acc += __shfl_down_sync(0xffffffffu, acc, o);
        if (lane == 0) logd[row] = acc;
    }
}

extern "C" void kernel_launch(void* const* d_in, const int* in_sizes, int n_in,
                              void* d_out, int out_size)
{
    const float* u     = (const float*)d_in[0];
    const float* w     = (const float*)d_in[1];
    const float* h     = (const float*)d_in[2];
    const float* dk    = (const float*)d_in[3];
    const int*   nodes = (const int*)  d_in[4];

    float* xout = (float*)d_out;
    float* logd = xout + (size_t)NROWS * DTOT;

    precompute_tables<<<1, 32>>>(w, h, dk);

    const int block = 256;
    const int grid  = 1184;   // ~8 blocks per SM worth of grid-stride work
    rqs_forward_kernel<<<grid, block>>>(u, nodes, xout, logd);
}